// round 16
// baseline (speedup 1.0000x reference)
#include <cuda_runtime.h>

#define RAD 5
#define WIN 11
#define TX 32
#define TY 8
#define PPT 2
#define TILE_H (TY * PPT)            // 16
#define HALO_W (TX + 2 * RAD)        // 42
#define HALO_H (TILE_H + 2 * RAD)    // 26
#define NPIX   (HALO_W * HALO_H)     // 1092
#define IMG_H 1024
#define IMG_W 1024

#define L2E 1.4426950408889634f

typedef unsigned long long ull;

__device__ __forceinline__ float ex2f(float x) {
    float r; asm("ex2.approx.f32 %0, %1;" : "=f"(r) : "f"(x)); return r;
}
__device__ __forceinline__ float lg2f(float x) {
    float r; asm("lg2.approx.f32 %0, %1;" : "=f"(r) : "f"(x)); return r;
}
__device__ __forceinline__ float fma_sat(float a, float b, float c) {
    float r; asm("fma.rn.sat.f32 %0, %1, %2, %3;" : "=f"(r) : "f"(a), "f"(b), "f"(c)); return r;
}
__device__ __forceinline__ ull pk2(float lo, float hi) {
    ull r; asm("mov.b64 %0, {%1, %2};" : "=l"(r) : "f"(lo), "f"(hi)); return r;
}
__device__ __forceinline__ void fma2(ull& d, ull a, ull b) {
    asm("fma.rn.f32x2 %0, %1, %2, %0;" : "+l"(d) : "l"(a), "l"(b));
}

// ---- compile-time LUT: ninvd = -1/dist, nwy = -(d2/8)*log2e ----
constexpr double csqrt_(double x) {
    double r = x > 1.0 ? x : 1.0;
    for (int i = 0; i < 64; ++i) r = 0.5 * (r + x / r);
    return r;
}
struct LutT {
    float ninvd[WIN * WIN];
    float nwy[WIN * WIN];
    constexpr LutT() : ninvd(), nwy() {
        for (int dy = -RAD; dy <= RAD; ++dy)
            for (int dx = -RAD; dx <= RAD; ++dx) {
                int i  = (dy + RAD) * WIN + (dx + RAD);
                int d2 = dx * dx + dy * dy;
                ninvd[i] = d2 ? (float)(-1.0 / csqrt_((double)d2)) : -1e30f;
                nwy[i]   = (float)(-(d2 * 0.125 * (double)L2E));
            }
    }
};

struct Ctx {
    const float4* sc;     // s_col:  {r, g, b, 1.0}
    const float4* sn;     // s_nrm:  {nx, ny, nz, z}
    int rowbase;          // (r0 + RAD) * HALO_W + tx
    float cnx[PPT], cny[PPT], cnz[PPT], czv[PPT], rcpdz2[PPT];
    ull acc01[PPT], acc23[PPT];   // {r,g}, {b,wsum}
};

template<int RY>
__device__ __forceinline__ void do_row(Ctx& c)
{
    const int rowb = c.rowbase + RY * HALO_W;
    #pragma unroll
    for (int dxi = 0; dxi < WIN; ++dxi) {
        float4 t = c.sc[rowb + dxi];
        float4 n = c.sn[rowb + dxi];
        ull t01 = pk2(t.x, t.y);          // aligned pair from LDS.128 — folds to reg alloc
        ull t23 = pk2(t.z, t.w);          // {b, 1.0}
        #pragma unroll
        for (int p = 0; p < PPT; ++p) {
            if (RY - p >= -RAD && RY - p <= RAD) {   // compile-time after unroll
                constexpr LutT L{};
                const float ninvd = L.ninvd[(RY - p + RAD) * WIN + dxi];  // immediate
                const float nwy   = L.nwy[(RY - p + RAD) * WIN + dxi];    // immediate
                float d   = fma_sat(c.cnx[p], n.x, fmaf(c.cny[p], n.y, c.cnz[p] * n.z));
                float lg  = lg2f(d);                           // -inf at 0 => w = 0
                float adz = fabsf(n.w - c.czv[p]);
                float tt  = adz * c.rcpdz2[p];                 // center: 0 * finite = 0
                float na  = fmaf(tt, ninvd, nwy);              // -(depth + spatial) exponent
                float wt  = ex2f(fmaf(lg, 128.0f, na));
                ull  w2 = pk2(wt, wt);
                fma2(c.acc01[p], t01, w2);
                fma2(c.acc23[p], t23, w2);
            }
        }
    }
}

__global__ __launch_bounds__(TX * TY, 4)
void bilateral_kernel(const float* __restrict__ col,
                      const float* __restrict__ nrm,
                      const float* __restrict__ zdz,
                      float* __restrict__ out)
{
    __shared__ float4 s_col[NPIX];         // {r, g, b, 1.0}
    __shared__ float4 s_nrm[NPIX];         // {nx, ny, nz, z}

    const int tx = threadIdx.x;
    const int ty = threadIdx.y;
    const int tid = ty * TX + tx;
    const int b  = blockIdx.z;
    const int x0 = blockIdx.x * TX;
    const int y0 = blockIdx.y * TILE_H;

    // ---- cooperative halo load ----
    for (int i = tid; i < NPIX; i += TX * TY) {
        int hy = i / HALO_W;
        int hx = i - hy * HALO_W;
        int gx = x0 + hx - RAD;
        int gy = y0 + hy - RAD;
        float4 cz = make_float4(0.f, 0.f, 0.f, 1.f);
        float4 nn = make_float4(0.f, 0.f, 0.f, 0.f);   // zero normal => sat(dot)=0 => lg2=-inf => w=0
        if (gx >= 0 && gx < IMG_W && gy >= 0 && gy < IMG_H) {
            int base = (b * IMG_H + gy) * IMG_W + gx;
            const float* cp = col + base * 3;
            cz.x = cp[0]; cz.y = cp[1]; cz.z = cp[2];
            const float* np = nrm + base * 3;
            nn.x = np[0]; nn.y = np[1]; nn.z = np[2];
            nn.w = zdz[base * 2];
        }
        s_col[i] = cz;
        s_nrm[i] = nn;
    }
    __syncthreads();

    // ---- per-pixel center data (2 vertically adjacent pixels per thread) ----
    const int r0 = ty * PPT;
    Ctx c;
    c.sc = s_col;
    c.sn = s_nrm;
    c.rowbase = (r0 + RAD) * HALO_W + tx;
    #pragma unroll
    for (int p = 0; p < PPT; ++p) {
        int ci = (r0 + p + RAD) * HALO_W + tx + RAD;
        float4 n = s_nrm[ci];
        c.cnx[p] = n.x; c.cny[p] = n.y; c.cnz[p] = n.z;
        c.czv[p] = n.w;
        int gy = y0 + r0 + p;
        int gx = x0 + tx;
        float cdz = zdz[((b * IMG_H + gy) * IMG_W + gx) * 2 + 1];
        c.rcpdz2[p] = fminf(L2E / cdz, 1e30f);   // finite: avoids 0*inf NaN at center tap
        c.acc01[p] = 0ull;
        c.acc23[p] = 0ull;
    }

    // ---- all 12 halo row positions, fully unrolled (LUT folds to immediates) ----
    do_row<-5>(c); do_row<-4>(c); do_row<-3>(c); do_row<-2>(c);
    do_row<-1>(c); do_row< 0>(c); do_row< 1>(c); do_row< 2>(c);
    do_row< 3>(c); do_row< 4>(c); do_row< 5>(c); do_row< 6>(c);

    // ---- writeback ----
    #pragma unroll
    for (int p = 0; p < PPT; ++p) {
        int gy = y0 + r0 + p;
        int gx = x0 + tx;
        int o = ((b * IMG_H + gy) * IMG_W + gx) * 3;
        float2 rg = *(float2*)&c.acc01[p];
        float2 bw = *(float2*)&c.acc23[p];
        float iw = 1.0f / bw.y;        // center tap guarantees wsum > 0
        out[o]     = rg.x * iw;
        out[o + 1] = rg.y * iw;
        out[o + 2] = bw.x * iw;
    }
}

extern "C" void kernel_launch(void* const* d_in, const int* in_sizes, int n_in,
                              void* d_out, int out_size)
{
    const float* col = (const float*)d_in[0];
    const float* nrm = (const float*)d_in[1];
    const float* zdz = (const float*)d_in[2];
    float* out = (float*)d_out;

    dim3 block(TX, TY);
    dim3 grid(IMG_W / TX, IMG_H / TILE_H, 4);
    bilateral_kernel<<<grid, block>>>(col, nrm, zdz, out);
}

// round 17
// speedup vs baseline: 1.6271x; 1.6271x over previous
#include <cuda_runtime.h>

#define RAD 5
#define WIN 11
#define TX 32
#define TY 8
#define PPT 2
#define TILE_H (TY * PPT)            // 16
#define HALO_W (TX + 2 * RAD)        // 42
#define HALO_H (TILE_H + 2 * RAD)    // 26
#define NPIX   (HALO_W * HALO_H)     // 1092
#define IMG_H 1024
#define IMG_W 1024

#define L2E 1.4426950408889634f

typedef unsigned long long ull;

__device__ __forceinline__ float ex2f(float x) {
    float r; asm("ex2.approx.f32 %0, %1;" : "=f"(r) : "f"(x)); return r;
}
__device__ __forceinline__ float lg2f(float x) {
    float r; asm("lg2.approx.f32 %0, %1;" : "=f"(r) : "f"(x)); return r;
}
__device__ __forceinline__ float fma_sat(float a, float b, float c) {
    float r; asm("fma.rn.sat.f32 %0, %1, %2, %3;" : "=f"(r) : "f"(a), "f"(b), "f"(c)); return r;
}
__device__ __forceinline__ ull pk2(float lo, float hi) {
    ull r; asm("mov.b64 %0, {%1, %2};" : "=l"(r) : "f"(lo), "f"(hi)); return r;
}
__device__ __forceinline__ void fma2(ull& d, ull a, ull b) {
    asm("fma.rn.f32x2 %0, %1, %2, %0;" : "+l"(d) : "l"(a), "l"(b));
}

// ---- compile-time LUT: ninvd = -1/dist, nwy = -(d2/8)*log2e ----
constexpr double csqrt_(double x) {
    double r = x > 1.0 ? x : 1.0;
    for (int i = 0; i < 64; ++i) r = 0.5 * (r + x / r);
    return r;
}
struct LutT {
    float ninvd[WIN * WIN];
    float nwy[WIN * WIN];
    constexpr LutT() : ninvd(), nwy() {
        for (int dy = -RAD; dy <= RAD; ++dy)
            for (int dx = -RAD; dx <= RAD; ++dx) {
                int i  = (dy + RAD) * WIN + (dx + RAD);
                int d2 = dx * dx + dy * dy;
                ninvd[i] = d2 ? (float)(-1.0 / csqrt_((double)d2)) : -1e30f;
                nwy[i]   = (float)(-(d2 * 0.125 * (double)L2E));
            }
    }
};

struct Ctx {
    const float4* sc;     // s_col:  {r, g, b, 1.0}
    const float4* sn;     // s_nrm:  {nx, ny, nz, z}
    int rowbase;          // (r0 + RAD) * HALO_W + tx
    float cnx[PPT], cny[PPT], cnz[PPT], czv[PPT], rcpdz2[PPT];
    ull acc01[PPT], acc23[PPT];   // {r,g}, {b,wsum}
};

template<int RY>
__device__ __forceinline__ void do_row(Ctx& c)
{
    const int rowb = c.rowbase + RY * HALO_W;
    #pragma unroll
    for (int dxi = 0; dxi < WIN; ++dxi) {
        float4 t = c.sc[rowb + dxi];
        float4 n = c.sn[rowb + dxi];
        ull t01 = pk2(t.x, t.y);          // aligned pair from LDS.128 — folds to reg alloc
        ull t23 = pk2(t.z, t.w);          // {b, 1.0}
        #pragma unroll
        for (int p = 0; p < PPT; ++p) {
            if (RY - p >= -RAD && RY - p <= RAD) {   // compile-time after unroll
                constexpr LutT L{};
                const float ninvd = L.ninvd[(RY - p + RAD) * WIN + dxi];  // immediate
                const float nwy   = L.nwy[(RY - p + RAD) * WIN + dxi];    // immediate
                float d   = fma_sat(c.cnx[p], n.x, fmaf(c.cny[p], n.y, c.cnz[p] * n.z));
                float lg  = lg2f(d);                           // -inf at 0 => w = 0
                float adz = fabsf(n.w - c.czv[p]);
                float tt  = adz * c.rcpdz2[p];                 // center: 0 * finite = 0
                float na  = fmaf(tt, ninvd, nwy);              // -(depth + spatial) exponent
                float wt  = ex2f(fmaf(lg, 128.0f, na));
                ull  w2 = pk2(wt, wt);
                fma2(c.acc01[p], t01, w2);
                fma2(c.acc23[p], t23, w2);
            }
        }
    }
}

__global__ __launch_bounds__(TX * TY, 4)
void bilateral_kernel(const float* __restrict__ col,
                      const float* __restrict__ nrm,
                      const float* __restrict__ zdz,
                      float* __restrict__ out)
{
    __shared__ float4 s_col[NPIX];         // {r, g, b, 1.0}
    __shared__ float4 s_nrm[NPIX];         // {nx, ny, nz, z}

    const int tx = threadIdx.x;
    const int ty = threadIdx.y;
    const int tid = ty * TX + tx;
    const int b  = blockIdx.z;
    const int x0 = blockIdx.x * TX;
    const int y0 = blockIdx.y * TILE_H;

    // ---- cooperative halo load ----
    for (int i = tid; i < NPIX; i += TX * TY) {
        int hy = i / HALO_W;
        int hx = i - hy * HALO_W;
        int gx = x0 + hx - RAD;
        int gy = y0 + hy - RAD;
        float4 cz = make_float4(0.f, 0.f, 0.f, 1.f);
        float4 nn = make_float4(0.f, 0.f, 0.f, 0.f);   // zero normal => sat(dot)=0 => lg2=-inf => w=0
        if (gx >= 0 && gx < IMG_W && gy >= 0 && gy < IMG_H) {
            int base = (b * IMG_H + gy) * IMG_W + gx;
            const float* cp = col + base * 3;
            cz.x = cp[0]; cz.y = cp[1]; cz.z = cp[2];
            const float* np = nrm + base * 3;
            nn.x = np[0]; nn.y = np[1]; nn.z = np[2];
            nn.w = zdz[base * 2];
        }
        s_col[i] = cz;
        s_nrm[i] = nn;
    }
    __syncthreads();

    // ---- per-pixel center data (2 vertically adjacent pixels per thread) ----
    const int r0 = ty * PPT;
    Ctx c;
    c.sc = s_col;
    c.sn = s_nrm;
    c.rowbase = (r0 + RAD) * HALO_W + tx;
    #pragma unroll
    for (int p = 0; p < PPT; ++p) {
        int ci = (r0 + p + RAD) * HALO_W + tx + RAD;
        float4 n = s_nrm[ci];
        c.cnx[p] = n.x; c.cny[p] = n.y; c.cnz[p] = n.z;
        c.czv[p] = n.w;
        int gy = y0 + r0 + p;
        int gx = x0 + tx;
        float cdz = zdz[((b * IMG_H + gy) * IMG_W + gx) * 2 + 1];
        c.rcpdz2[p] = fminf(L2E / cdz, 1e30f);   // finite: avoids 0*inf NaN at center tap
        c.acc01[p] = 0ull;
        c.acc23[p] = 0ull;
    }

    // ---- all 12 halo row positions, fully unrolled (LUT folds to immediates) ----
    do_row<-5>(c); do_row<-4>(c); do_row<-3>(c); do_row<-2>(c);
    do_row<-1>(c); do_row< 0>(c); do_row< 1>(c); do_row< 2>(c);
    do_row< 3>(c); do_row< 4>(c); do_row< 5>(c); do_row< 6>(c);

    // ---- writeback ----
    #pragma unroll
    for (int p = 0; p < PPT; ++p) {
        int gy = y0 + r0 + p;
        int gx = x0 + tx;
        int o = ((b * IMG_H + gy) * IMG_W + gx) * 3;
        float2 rg = *(float2*)&c.acc01[p];
        float2 bw = *(float2*)&c.acc23[p];
        float iw = 1.0f / bw.y;        // center tap guarantees wsum > 0
        out[o]     = rg.x * iw;
        out[o + 1] = rg.y * iw;
        out[o + 2] = bw.x * iw;
    }
}

extern "C" void kernel_launch(void* const* d_in, const int* in_sizes, int n_in,
                              void* d_out, int out_size)
{
    const float* col = (const float*)d_in[0];
    const float* nrm = (const float*)d_in[1];
    const float* zdz = (const float*)d_in[2];
    float* out = (float*)d_out;

    dim3 block(TX, TY);
    dim3 grid(IMG_W / TX, IMG_H / TILE_H, 4);
    bilateral_kernel<<<grid, block>>>(col, nrm, zdz, out);
}